// round 3
// baseline (speedup 1.0000x reference)
#include <cuda_runtime.h>

// Geometric controller: 13-float state, 33-float ref_state, 3x3 J -> 4 floats.
// Single-thread scalar fp32 kernel, everything in registers.
// NOTE: the reference intentionally uses des_acc_ddd in ev_ddd and
// des_acc_dddd in ev_dddd (breaking the derivative-index pattern) — match it.

#define KP   16.0f
#define KV   5.6f
#define KORI 8.81f
#define KW   2.54f
#define MASSC 4.34f
#define GRAV 9.81f

__device__ __forceinline__ void cross3(const float* a, const float* b, float* o) {
    o[0] = a[1]*b[2] - a[2]*b[1];
    o[1] = a[2]*b[0] - a[0]*b[2];
    o[2] = a[0]*b[1] - a[1]*b[0];
}
__device__ __forceinline__ float dot3(const float* a, const float* b) {
    return a[0]*b[0] + a[1]*b[1] + a[2]*b[2];
}
__device__ __forceinline__ void matvec(const float R[3][3], const float* v, float* o) {
    #pragma unroll
    for (int i = 0; i < 3; i++)
        o[i] = R[i][0]*v[0] + R[i][1]*v[1] + R[i][2]*v[2];
}
__device__ __forceinline__ void matTvec(const float R[3][3], const float* v, float* o) {
    #pragma unroll
    for (int i = 0; i < 3; i++)
        o[i] = R[0][i]*v[0] + R[1][i]*v[1] + R[2][i]*v[2];
}
// o = A^T * B
__device__ __forceinline__ void matTmat(const float A[3][3], const float B[3][3], float o[3][3]) {
    #pragma unroll
    for (int i = 0; i < 3; i++)
        #pragma unroll
        for (int j = 0; j < 3; j++)
            o[i][j] = A[0][i]*B[0][j] + A[1][i]*B[1][j] + A[2][i]*B[2][j];
}
// o = A * B
__device__ __forceinline__ void matmat(const float A[3][3], const float B[3][3], float o[3][3]) {
    #pragma unroll
    for (int i = 0; i < 3; i++)
        #pragma unroll
        for (int j = 0; j < 3; j++)
            o[i][j] = A[i][0]*B[0][j] + A[i][1]*B[1][j] + A[i][2]*B[2][j];
}
__device__ __forceinline__ void skew(const float* v, float o[3][3]) {
    o[0][0] = 0.f;   o[0][1] = -v[2]; o[0][2] =  v[1];
    o[1][0] =  v[2]; o[1][1] = 0.f;   o[1][2] = -v[0];
    o[2][0] = -v[1]; o[2][1] =  v[0]; o[2][2] = 0.f;
}
__device__ __forceinline__ void skew2vec(const float m[3][3], float* o) {
    o[0] = -m[1][2];
    o[1] =  m[0][2];
    o[2] = -m[0][1];
}
// v = sign * v / ||v||
__device__ __forceinline__ void normalize_s(float* v, float sign) {
    float s = sign * rsqrtf(dot3(v, v));
    v[0] *= s; v[1] *= s; v[2] *= s;
}

__global__ void geometric_controller_kernel(const float* __restrict__ state,
                                            const float* __restrict__ ref,
                                            const float* __restrict__ Jm,
                                            float* __restrict__ out) {
    const float m = MASSC, g = GRAV;
    const float kp = KP, kv = KV, kori = KORI, kw = KW;

    // ---- load inputs ----
    float pos[3] = { state[0], state[1], state[2] };
    float qx = state[3], qy = state[4], qz = state[5], qw = state[6];
    float vel[3] = { state[7], state[8], state[9] };
    float w[3]   = { state[10], state[11], state[12] };

    float des_pos[3], des_vel[3];
    float des_acc[5][3];   // acc, acc_d, acc_dd, acc_ddd, acc_dddd
    float des_b1[4][3];    // b1, b1_d, b1_dd, b1_ddd
    #pragma unroll
    for (int i = 0; i < 3; i++) {
        des_pos[i] = ref[0 + i];
        des_vel[i] = ref[3 + i];
        #pragma unroll
        for (int k = 0; k < 5; k++) des_acc[k][i] = ref[3*(2+k) + i];
        #pragma unroll
        for (int k = 0; k < 4; k++) des_b1[k][i]  = ref[3*(7+k) + i];
    }
    float J[3][3];
    #pragma unroll
    for (int i = 0; i < 3; i++)
        #pragma unroll
        for (int j = 0; j < 3; j++)
            J[i][j] = Jm[i*3 + j];

    // ---- rotation matrix from quaternion (x,y,z,w) ----
    float R[3][3];
    R[0][0] = 1.f - 2.f*(qy*qy + qz*qz); R[0][1] = 2.f*(qx*qy - qz*qw);       R[0][2] = 2.f*(qx*qz + qy*qw);
    R[1][0] = 2.f*(qx*qy + qz*qw);       R[1][1] = 1.f - 2.f*(qx*qx + qz*qz); R[1][2] = 2.f*(qy*qz - qx*qw);
    R[2][0] = 2.f*(qx*qz - qy*qw);       R[2][1] = 2.f*(qy*qz + qx*qw);       R[2][2] = 1.f - 2.f*(qx*qx + qy*qy);

    // b3 chain: b3^{(k)} = R @ (w x)^k e3
    const float e3[3] = { 0.f, 0.f, 1.f };
    float u[4][3];                 // (w x)^k e3 for k=0..3
    u[0][0] = 0.f; u[0][1] = 0.f; u[0][2] = 1.f;
    cross3(w, u[0], u[1]);
    cross3(w, u[1], u[2]);
    cross3(w, u[2], u[3]);
    float b3k[4][3];               // b3, b3_d, b3_dd, b3_ddd
    #pragma unroll
    for (int k = 0; k < 4; k++) matvec(R, u[k], b3k[k]);

    // ---- des_b3 derivative chain ----
    float db3[5][3];               // des_b3 .. des_b3_dddd (pre-normalization)
    float thrust, thrust_d, thrust_dd, thrust_ddd;

    #pragma unroll
    for (int i = 0; i < 3; i++)
        db3[0][i] = -(kp*(pos[i]-des_pos[i]) + kv*(vel[i]-des_vel[i])) - m*g*e3[i] + m*des_acc[0][i];
    thrust = -dot3(db3[0], b3k[0]);

    float ev_d[3], ev_dd[3], ev_ddd[3], ev_dddd[3];
    #pragma unroll
    for (int i = 0; i < 3; i++)
        ev_d[i] = g*e3[i] - (thrust/m)*b3k[0][i] - des_acc[0][i];
    #pragma unroll
    for (int i = 0; i < 3; i++)
        db3[1][i] = -kp*(vel[i]-des_vel[i]) - kv*ev_d[i] + m*des_acc[1][i];
    thrust_d = -dot3(db3[1], b3k[0]) - dot3(db3[0], b3k[1]);

    #pragma unroll
    for (int i = 0; i < 3; i++)
        ev_dd[i] = (-thrust_d*b3k[0][i] - thrust*b3k[1][i]) / m - des_acc[1][i];
    #pragma unroll
    for (int i = 0; i < 3; i++)
        db3[2][i] = -kp*ev_d[i] - kv*ev_dd[i] + m*des_acc[2][i];
    thrust_dd = -dot3(db3[2], b3k[0]) - 2.f*dot3(db3[1], b3k[1]) - dot3(db3[0], b3k[2]);

    // NOTE: reference subtracts des_acc_ddd (index 3) here, not des_acc_dd.
    #pragma unroll
    for (int i = 0; i < 3; i++)
        ev_ddd[i] = (-thrust_dd*b3k[0][i] - 2.f*thrust_d*b3k[1][i] - thrust*b3k[2][i]) / m - des_acc[3][i];
    #pragma unroll
    for (int i = 0; i < 3; i++)
        db3[3][i] = -kp*ev_dd[i] - kv*ev_ddd[i] + m*des_acc[3][i];
    thrust_ddd = -dot3(db3[3], b3k[0]) - 3.f*dot3(db3[2], b3k[1]) - 3.f*dot3(db3[1], b3k[2]) - dot3(db3[0], b3k[3]);

    // NOTE: reference subtracts des_acc_dddd (index 4) here, not des_acc_ddd.
    #pragma unroll
    for (int i = 0; i < 3; i++)
        ev_dddd[i] = (-thrust_ddd*b3k[0][i] - 3.f*thrust_dd*b3k[1][i] - 3.f*thrust_d*b3k[2][i] - thrust*b3k[3][i]) / m
                     - des_acc[4][i];
    #pragma unroll
    for (int i = 0; i < 3; i++)
        db3[4][i] = -kp*ev_ddd[i] - kv*ev_dddd[i] + m*des_acc[4][i];

    // normalize (negated)
    #pragma unroll
    for (int k = 0; k < 5; k++) normalize_s(db3[k], -1.f);

    // ---- b2 chain: b2^{(k)} = sum_i C(k,i) cross(db3^{(k-i)}, des_b1^{(i)}), i<=3 ----
    const float binom[5][5] = {
        {1,0,0,0,0},{1,1,0,0,0},{1,2,1,0,0},{1,3,3,1,0},{1,4,6,4,1}
    };
    float b2[5][3];
    #pragma unroll
    for (int k = 0; k < 5; k++) {
        float acc[3] = {0.f, 0.f, 0.f};
        #pragma unroll
        for (int i = 0; i < 4; i++) {          // des_b1 has derivatives 0..3 only
            if (i > k) continue;
            float c = binom[k][i];
            float t[3];
            cross3(db3[k - i], des_b1[i], t);
            acc[0] += c * t[0]; acc[1] += c * t[1]; acc[2] += c * t[2];
        }
        b2[k][0] = acc[0]; b2[k][1] = acc[1]; b2[k][2] = acc[2];
    }
    #pragma unroll
    for (int k = 0; k < 5; k++) normalize_s(b2[k], 1.f);

    // ---- b1 chain: b1^{(k)} = sum_i C(k,i) cross(b2^{(k-i)}, db3^{(i)}) ----
    float b1[5][3];
    #pragma unroll
    for (int k = 0; k < 5; k++) {
        float acc[3] = {0.f, 0.f, 0.f};
        #pragma unroll
        for (int i = 0; i <= 4; i++) {
            if (i > k) continue;
            float c = binom[k][i];
            float t[3];
            cross3(b2[k - i], db3[i], t);
            acc[0] += c * t[0]; acc[1] += c * t[1]; acc[2] += c * t[2];
        }
        b1[k][0] = acc[0]; b1[k][1] = acc[1]; b1[k][2] = acc[2];
    }
    #pragma unroll
    for (int k = 0; k < 5; k++) normalize_s(b1[k], 1.f);

    // ---- desired rotation matrices (columns b1, b2, db3) ----
    float Rd[5][3][3];
    #pragma unroll
    for (int k = 0; k < 5; k++)
        #pragma unroll
        for (int i = 0; i < 3; i++) {
            Rd[k][i][0] = b1[k][i];
            Rd[k][i][1] = b2[k][i];
            Rd[k][i][2] = db3[k][i];
        }

    // ---- angular derivatives ----
    float tmpM[3][3], tmpM2[3][3], tmpM3[3][3];
    float w_d[3], a_d[3], j_d[3], s_d[3];

    matTmat(Rd[0], Rd[1], tmpM);
    skew2vec(tmpM, w_d);
    float W[3][3];
    skew(w_d, W);

    // a_d = skew2vec(Rd^T Rd_dd - W W)
    matTmat(Rd[0], Rd[2], tmpM);
    matmat(W, W, tmpM2);
    #pragma unroll
    for (int i = 0; i < 3; i++)
        #pragma unroll
        for (int j = 0; j < 3; j++)
            tmpM[i][j] -= tmpM2[i][j];
    skew2vec(tmpM, a_d);

    // j_d = skew2vec(Rd^T Rd_ddd - 3 W skew(a_d))
    float Sa[3][3];
    skew(a_d, Sa);
    matTmat(Rd[0], Rd[3], tmpM);
    matmat(W, Sa, tmpM2);
    #pragma unroll
    for (int i = 0; i < 3; i++)
        #pragma unroll
        for (int j = 0; j < 3; j++)
            tmpM[i][j] -= 3.f * tmpM2[i][j];
    skew2vec(tmpM, j_d);

    // s_d = skew2vec(Rd^T Rd_dddd - 4 W skew(j_d) - 3 skew(a_d) skew(a_d))
    float Sj[3][3];
    skew(j_d, Sj);
    matTmat(Rd[0], Rd[4], tmpM);
    matmat(W, Sj, tmpM2);
    matmat(Sa, Sa, tmpM3);
    #pragma unroll
    for (int i = 0; i < 3; i++)
        #pragma unroll
        for (int j = 0; j < 3; j++)
            tmpM[i][j] -= 4.f * tmpM2[i][j] + 3.f * tmpM3[i][j];
    skew2vec(tmpM, s_d);

    // ---- errors and moment ----
    float e_R[3];
    {
        float A[3][3], B[3][3];
        matTmat(Rd[0], R, A);     // Rd^T R
        matTmat(R, Rd[0], B);     // R^T Rd
        #pragma unroll
        for (int i = 0; i < 3; i++)
            #pragma unroll
            for (int j = 0; j < 3; j++)
                A[i][j] -= B[i][j];
        skew2vec(A, e_R);
        e_R[0] *= 0.5f; e_R[1] *= 0.5f; e_R[2] *= 0.5f;
    }

    float e_w[3];
    {
        float t1[3], t2[3];
        matvec(Rd[0], w_d, t1);
        matTvec(R, t1, t2);
        e_w[0] = w[0] - t2[0]; e_w[1] = w[1] - t2[1]; e_w[2] = w[2] - t2[2];
    }

    float Jw[3];
    matvec(J, w, Jw);
    float wxJw[3];
    cross3(w, Jw, wxJw);

    float M[3];
    #pragma unroll
    for (int i = 0; i < 3; i++)
        M[i] = -(kori*e_R[i] + kw*e_w[i]) + wxJw[i];

    // temp_M = wx @ (R^T @ (Rd @ (w_d - a_d - j_d - s_d)))
    float vsum[3], t1[3], t2[3], tM[3], JtM[3];
    #pragma unroll
    for (int i = 0; i < 3; i++) vsum[i] = w_d[i] - a_d[i] - j_d[i] - s_d[i];
    matvec(Rd[0], vsum, t1);
    matTvec(R, t1, t2);
    cross3(w, t2, tM);          // skew(w) @ t2 == w x t2
    matvec(J, tM, JtM);
    #pragma unroll
    for (int i = 0; i < 3; i++) M[i] -= JtM[i];

    out[0] = fmaxf(0.f, thrust);
    out[1] = M[0];
    out[2] = M[1];
    out[3] = M[2];
}

extern "C" void kernel_launch(void* const* d_in, const int* in_sizes, int n_in,
                              void* d_out, int out_size) {
    const float* state = (const float*)d_in[0];
    const float* ref   = (const float*)d_in[1];
    const float* J     = (const float*)d_in[2];
    float* out = (float*)d_out;
    geometric_controller_kernel<<<1, 1>>>(state, ref, J, out);
}

// round 4
// speedup vs baseline: 1.4626x; 1.4626x over previous
#include <cuda_runtime.h>

// Geometric controller: 13-float state, 33-float ref_state, 3x3 J -> 4 floats.
// Single-thread fp32 kernel, all in registers (__launch_bounds__(1) -> 255 regs, no spills).
// Algebraically pruned:
//  - skew2vec(Rd0^T Rdk - corr) needs only 3 dot products (entries [1][2],[0][2],[0][1])
//  - b1 derivative chain is dead code (only b1[0] is ever read)
//  - skew(a)skew(b) = b a^T - (a.b) I  -> all 3x3 matmats become scalar products
// NOTE: reference uses des_acc_ddd in ev_ddd and des_acc_dddd in ev_dddd
// (breaking the derivative-index pattern) — matched deliberately.

#define KP    16.0f
#define KV    5.6f
#define KORI  8.81f
#define KW    2.54f
#define MASSC 4.34f
#define INV_M (1.0f / 4.34f)
#define GRAV  9.81f

__device__ __forceinline__ void cross3(const float* a, const float* b, float* o) {
    o[0] = a[1]*b[2] - a[2]*b[1];
    o[1] = a[2]*b[0] - a[0]*b[2];
    o[2] = a[0]*b[1] - a[1]*b[0];
}
__device__ __forceinline__ float dot3(const float* a, const float* b) {
    return a[0]*b[0] + a[1]*b[1] + a[2]*b[2];
}
// v = sign * v / ||v||
__device__ __forceinline__ void normalize_s(float* v, float sign) {
    float s = sign * rsqrtf(dot3(v, v));
    v[0] *= s; v[1] *= s; v[2] *= s;
}

__global__ void __launch_bounds__(1, 1)
geometric_controller_kernel(const float* __restrict__ state,
                            const float* __restrict__ ref,
                            const float* __restrict__ Jm,
                            float* __restrict__ out) {
    const float m = MASSC, g = GRAV;
    const float kp = KP, kv = KV, kori = KORI, kw = KW;

    // ---- load inputs ----
    float pos[3] = { state[0], state[1], state[2] };
    float qx = state[3], qy = state[4], qz = state[5], qw = state[6];
    float vel[3] = { state[7], state[8], state[9] };
    float w[3]   = { state[10], state[11], state[12] };

    float des_pos[3], des_vel[3];
    float des_acc[5][3];   // acc .. acc_dddd
    float des_b1[4][3];    // b1 .. b1_ddd (reference's desired heading derivs)
    #pragma unroll
    for (int i = 0; i < 3; i++) {
        des_pos[i] = ref[0 + i];
        des_vel[i] = ref[3 + i];
        #pragma unroll
        for (int k = 0; k < 5; k++) des_acc[k][i] = ref[3*(2+k) + i];
        #pragma unroll
        for (int k = 0; k < 4; k++) des_b1[k][i]  = ref[3*(7+k) + i];
    }
    float J[3][3];
    #pragma unroll
    for (int i = 0; i < 3; i++)
        #pragma unroll
        for (int j = 0; j < 3; j++)
            J[i][j] = Jm[i*3 + j];

    // ---- rotation matrix from quaternion (x,y,z,w) ----
    float R[3][3];
    R[0][0] = 1.f - 2.f*(qy*qy + qz*qz); R[0][1] = 2.f*(qx*qy - qz*qw);       R[0][2] = 2.f*(qx*qz + qy*qw);
    R[1][0] = 2.f*(qx*qy + qz*qw);       R[1][1] = 1.f - 2.f*(qx*qx + qz*qz); R[1][2] = 2.f*(qy*qz - qx*qw);
    R[2][0] = 2.f*(qx*qz - qy*qw);       R[2][1] = 2.f*(qy*qz + qx*qw);       R[2][2] = 1.f - 2.f*(qx*qx + qy*qy);

    // b3 chain: b3^{(k)} = R @ (w x)^k e3
    float u[4][3];
    u[0][0] = 0.f; u[0][1] = 0.f; u[0][2] = 1.f;
    cross3(w, u[0], u[1]);
    cross3(w, u[1], u[2]);
    cross3(w, u[2], u[3]);
    float b3k[4][3];
    #pragma unroll
    for (int k = 0; k < 4; k++)
        #pragma unroll
        for (int i = 0; i < 3; i++)
            b3k[k][i] = R[i][0]*u[k][0] + R[i][1]*u[k][1] + R[i][2]*u[k][2];

    // ---- des_b3 derivative chain ----
    float db3[5][3];
    float thrust, thrust_d, thrust_dd, thrust_ddd;

    #pragma unroll
    for (int i = 0; i < 3; i++) {
        float gz = (i == 2) ? m*g : 0.f;
        db3[0][i] = -(kp*(pos[i]-des_pos[i]) + kv*(vel[i]-des_vel[i])) - gz + m*des_acc[0][i];
    }
    thrust = -dot3(db3[0], b3k[0]);

    float ev_d[3], ev_dd[3], ev_ddd[3], ev_dddd[3];
    float t_over_m = thrust * INV_M;
    #pragma unroll
    for (int i = 0; i < 3; i++) {
        float gz = (i == 2) ? g : 0.f;
        ev_d[i] = gz - t_over_m*b3k[0][i] - des_acc[0][i];
    }
    #pragma unroll
    for (int i = 0; i < 3; i++)
        db3[1][i] = -kp*(vel[i]-des_vel[i]) - kv*ev_d[i] + m*des_acc[1][i];
    thrust_d = -dot3(db3[1], b3k[0]) - dot3(db3[0], b3k[1]);

    #pragma unroll
    for (int i = 0; i < 3; i++)
        ev_dd[i] = (-thrust_d*b3k[0][i] - thrust*b3k[1][i]) * INV_M - des_acc[1][i];
    #pragma unroll
    for (int i = 0; i < 3; i++)
        db3[2][i] = -kp*ev_d[i] - kv*ev_dd[i] + m*des_acc[2][i];
    thrust_dd = -dot3(db3[2], b3k[0]) - 2.f*dot3(db3[1], b3k[1]) - dot3(db3[0], b3k[2]);

    // reference subtracts des_acc_ddd (index 3) here
    #pragma unroll
    for (int i = 0; i < 3; i++)
        ev_ddd[i] = (-thrust_dd*b3k[0][i] - 2.f*thrust_d*b3k[1][i] - thrust*b3k[2][i]) * INV_M - des_acc[3][i];
    #pragma unroll
    for (int i = 0; i < 3; i++)
        db3[3][i] = -kp*ev_dd[i] - kv*ev_ddd[i] + m*des_acc[3][i];
    thrust_ddd = -dot3(db3[3], b3k[0]) - 3.f*dot3(db3[2], b3k[1]) - 3.f*dot3(db3[1], b3k[2]) - dot3(db3[0], b3k[3]);

    // reference subtracts des_acc_dddd (index 4) here
    #pragma unroll
    for (int i = 0; i < 3; i++)
        ev_dddd[i] = (-thrust_ddd*b3k[0][i] - 3.f*thrust_dd*b3k[1][i] - 3.f*thrust_d*b3k[2][i] - thrust*b3k[3][i]) * INV_M
                     - des_acc[4][i];
    #pragma unroll
    for (int i = 0; i < 3; i++)
        db3[4][i] = -kp*ev_ddd[i] - kv*ev_dddd[i] + m*des_acc[4][i];

    #pragma unroll
    for (int k = 0; k < 5; k++) normalize_s(db3[k], -1.f);

    // ---- b2 chain: b2^{(k)} = sum_i C(k,i) cross(db3^{(k-i)}, des_b1^{(i)}), i<=3 ----
    const float binom[5][5] = {
        {1,0,0,0,0},{1,1,0,0,0},{1,2,1,0,0},{1,3,3,1,0},{1,4,6,4,1}
    };
    float b2[5][3];
    #pragma unroll
    for (int k = 0; k < 5; k++) {
        float acc[3] = {0.f, 0.f, 0.f};
        #pragma unroll
        for (int i = 0; i < 4; i++) {
            if (i > k) continue;
            float c = binom[k][i];
            float t[3];
            cross3(db3[k - i], des_b1[i], t);
            acc[0] += c * t[0]; acc[1] += c * t[1]; acc[2] += c * t[2];
        }
        b2[k][0] = acc[0]; b2[k][1] = acc[1]; b2[k][2] = acc[2];
    }
    #pragma unroll
    for (int k = 0; k < 5; k++) normalize_s(b2[k], 1.f);

    // ---- b1[0] only (b1 derivatives are never read downstream) ----
    float b1_0[3];
    cross3(b2[0], db3[0], b1_0);
    normalize_s(b1_0, 1.f);

    // ---- angular derivatives via 3-dot skew2vec forms ----
    // skew2vec(Rd0^T Rdk)[0] = -(b2_0 . db3_k); [1] = b1_0 . db3_k; [2] = -(b1_0 . b2_k)
    float w_d[3], a_d[3], j_d[3], s_d[3];

    w_d[0] = -dot3(b2[0], db3[1]);
    w_d[1] =  dot3(b1_0,  db3[1]);
    w_d[2] = -dot3(b1_0,  b2[1]);

    // W@W = w_d w_d^T - |w_d|^2 I : off-diag [1][2]=w1w2, [0][2]=w0w2, [0][1]=w0w1
    a_d[0] = -(dot3(b2[0], db3[2]) - w_d[1]*w_d[2]);
    a_d[1] =  (dot3(b1_0,  db3[2]) - w_d[0]*w_d[2]);
    a_d[2] = -(dot3(b1_0,  b2[2])  - w_d[0]*w_d[1]);

    // W@Sa = a_d w_d^T - (w_d.a_d) I : off-diag [i][j] = a_d[i]*w_d[j]
    j_d[0] = -(dot3(b2[0], db3[3]) - 3.f*a_d[1]*w_d[2]);
    j_d[1] =  (dot3(b1_0,  db3[3]) - 3.f*a_d[0]*w_d[2]);
    j_d[2] = -(dot3(b1_0,  b2[3])  - 3.f*a_d[0]*w_d[1]);

    // W@Sj off-diag [i][j] = j_d[i]*w_d[j];  Sa@Sa off-diag [i][j] = a_d[i]*a_d[j]
    s_d[0] = -(dot3(b2[0], db3[4]) - 4.f*j_d[1]*w_d[2] - 3.f*a_d[1]*a_d[2]);
    s_d[1] =  (dot3(b1_0,  db3[4]) - 4.f*j_d[0]*w_d[2] - 3.f*a_d[0]*a_d[2]);
    s_d[2] = -(dot3(b1_0,  b2[4])  - 4.f*j_d[0]*w_d[1] - 3.f*a_d[0]*a_d[1]);

    // ---- attitude error e_R = 0.5 skew2vec(Rd^T R - R^T Rd) ----
    float Rc0[3] = { R[0][0], R[1][0], R[2][0] };
    float Rc1[3] = { R[0][1], R[1][1], R[2][1] };
    float Rc2[3] = { R[0][2], R[1][2], R[2][2] };
    float e_R[3];
    e_R[0] = -0.5f * (dot3(b2[0], Rc2) - dot3(Rc1, db3[0]));
    e_R[1] =  0.5f * (dot3(b1_0,  Rc2) - dot3(Rc0, db3[0]));
    e_R[2] = -0.5f * (dot3(b1_0,  Rc1) - dot3(Rc0, b2[0]));

    // ---- e_w = w - R^T (Rd0 @ w_d) ----
    float Rdw[3], t2[3], e_w[3];
    #pragma unroll
    for (int i = 0; i < 3; i++)
        Rdw[i] = b1_0[i]*w_d[0] + b2[0][i]*w_d[1] + db3[0][i]*w_d[2];
    t2[0] = dot3(Rc0, Rdw); t2[1] = dot3(Rc1, Rdw); t2[2] = dot3(Rc2, Rdw);
    #pragma unroll
    for (int i = 0; i < 3; i++) e_w[i] = w[i] - t2[i];

    // ---- moment ----
    float Jw[3];
    #pragma unroll
    for (int i = 0; i < 3; i++) Jw[i] = J[i][0]*w[0] + J[i][1]*w[1] + J[i][2]*w[2];
    float wxJw[3];
    cross3(w, Jw, wxJw);

    float M[3];
    #pragma unroll
    for (int i = 0; i < 3; i++)
        M[i] = -(kori*e_R[i] + kw*e_w[i]) + wxJw[i];

    // temp_M = w x (R^T (Rd0 @ (w_d - a_d - j_d - s_d)))
    float vsum[3], t1[3], tM[3], JtM[3];
    #pragma unroll
    for (int i = 0; i < 3; i++) vsum[i] = w_d[i] - a_d[i] - j_d[i] - s_d[i];
    #pragma unroll
    for (int i = 0; i < 3; i++)
        t1[i] = b1_0[i]*vsum[0] + b2[0][i]*vsum[1] + db3[0][i]*vsum[2];
    t2[0] = dot3(Rc0, t1); t2[1] = dot3(Rc1, t1); t2[2] = dot3(Rc2, t1);
    cross3(w, t2, tM);
    #pragma unroll
    for (int i = 0; i < 3; i++)
        JtM[i] = J[i][0]*tM[0] + J[i][1]*tM[1] + J[i][2]*tM[2];
    #pragma unroll
    for (int i = 0; i < 3; i++) M[i] -= JtM[i];

    out[0] = fmaxf(0.f, thrust);
    out[1] = M[0];
    out[2] = M[1];
    out[3] = M[2];
}

extern "C" void kernel_launch(void* const* d_in, const int* in_sizes, int n_in,
                              void* d_out, int out_size) {
    const float* state = (const float*)d_in[0];
    const float* ref   = (const float*)d_in[1];
    const float* J     = (const float*)d_in[2];
    float* out = (float*)d_out;
    geometric_controller_kernel<<<1, 1>>>(state, ref, J, out);
}